// round 1
// baseline (speedup 1.0000x reference)
#include <cuda_runtime.h>
#include <cstddef>

#define VOCAB 100000
#define EMBED 128
#define STORY 50
#define SENT  64
#define BATCH 64
#define QLEN  16
#define HOPS  3

#define VT     64
#define NBLK_V ((VOCAB + VT - 1) / VT)   // 1563

// ---------------- scratch (device globals: allocation-free) ----------------
__device__ float g_u[BATCH * EMBED];
__device__ float g_mw[HOPS][BATCH * STORY * EMBED];   // m (pe-weighted sum + TA), tables 0..2
__device__ float g_cs[HOPS][BATCH * STORY * EMBED];   // c (plain sum + TC), tables 1..3
__device__ float g_pmax[BATCH * NBLK_V];
__device__ float g_psum[BATCH * NBLK_V];
__device__ float g_lse[BATCH];

// ---------------- packed fp32x2 FMA (Blackwell) ----------------
__device__ __forceinline__ void ffma2(unsigned long long& d, unsigned long long a,
                                      unsigned long long b) {
    asm("fma.rn.f32x2 %0, %1, %2, %0;" : "+l"(d) : "l"(a), "l"(b));
}

// ---------------- K1: u0 = sum_j A[0][q[b,j]] ----------------
__global__ void k_u0(const int* __restrict__ q, const float* __restrict__ A) {
    const int b = blockIdx.x;
    const int k = threadIdx.x;   // 128
    float acc = 0.f;
#pragma unroll
    for (int j = 0; j < QLEN; ++j) {
        int idx = __ldg(q + b * QLEN + j);
        acc += __ldg(A + (size_t)idx * EMBED + k);
    }
    g_u[b * EMBED + k] = acc;
}

// ---------------- K2: fused gather-reduce per (b,s,h) ----------------
// One gather of table h serves BOTH m of hop h (pe-weighted) and c of hop h-1 (plain).
__global__ void k_gather(const int* __restrict__ x, const float* __restrict__ A,
                         const float* __restrict__ TA, const float* __restrict__ TC) {
    const int bs = blockIdx.x;        // 0..BATCH*STORY-1
    const int h  = blockIdx.y;        // 0..3
    const int s  = bs % STORY;
    const int t  = threadIdx.x;       // 128

    __shared__ int idx[SENT];
    __shared__ float4 redw[4][32];
    __shared__ float4 redp[4][32];

    if (t < SENT) idx[t] = x[bs * SENT + t];
    __syncthreads();

    const float* __restrict__ Ah = A + (size_t)h * VOCAB * EMBED;
    const int c4 = (t & 31) * 4;      // k column (float4)
    const int js = t >> 5;            // j slice 0..3

    const float kf0 = (float)(c4 + 1) * (1.0f / EMBED);
    const float kf1 = (float)(c4 + 2) * (1.0f / EMBED);
    const float kf2 = (float)(c4 + 3) * (1.0f / EMBED);
    const float kf3 = (float)(c4 + 4) * (1.0f / EMBED);

    float4 wp = make_float4(0.f, 0.f, 0.f, 0.f);
    float4 pp = make_float4(0.f, 0.f, 0.f, 0.f);

#pragma unroll 4
    for (int j = js; j < SENT; j += 4) {
        const float4 a = *(const float4*)(Ah + (size_t)idx[j] * EMBED + c4);
        const float fj = (float)(j + 1) * (1.0f / SENT);
        const float g  = 1.0f - 2.0f * fj;
        const float base = 1.0f - fj;
        wp.x = fmaf(a.x, fmaf(-kf0, g, base), wp.x);
        wp.y = fmaf(a.y, fmaf(-kf1, g, base), wp.y);
        wp.z = fmaf(a.z, fmaf(-kf2, g, base), wp.z);
        wp.w = fmaf(a.w, fmaf(-kf3, g, base), wp.w);
        pp.x += a.x; pp.y += a.y; pp.z += a.z; pp.w += a.w;
    }

    redw[js][t & 31] = wp;
    redp[js][t & 31] = pp;
    __syncthreads();

    if (t < 32) {
        float4 w = redw[0][t], p = redp[0][t];
#pragma unroll
        for (int r = 1; r < 4; ++r) {
            float4 w2 = redw[r][t], p2 = redp[r][t];
            w.x += w2.x; w.y += w2.y; w.z += w2.z; w.w += w2.w;
            p.x += p2.x; p.y += p2.y; p.z += p2.z; p.w += p2.w;
        }
        const int k0 = t * 4;
        if (h < HOPS) {
            const float4 ta4 = *(const float4*)(TA + s * EMBED + k0);
            w.x += ta4.x; w.y += ta4.y; w.z += ta4.z; w.w += ta4.w;
            *(float4*)(g_mw[h] + (size_t)bs * EMBED + k0) = w;
        }
        if (h > 0) {
            const float4 tc4 = *(const float4*)(TC + s * EMBED + k0);
            p.x += tc4.x; p.y += tc4.y; p.z += tc4.z; p.w += tc4.w;
            *(float4*)(g_cs[h - 1] + (size_t)bs * EMBED + k0) = p;
        }
    }
}

// ---------------- K3: 3 hops, per-batch independent ----------------
__global__ void k_hops() {
    const int b = blockIdx.x;
    const int t = threadIdx.x;     // 128
    const int w = t >> 5, lane = t & 31;

    __shared__ float u[EMBED];
    __shared__ float sc[STORY];

    u[t] = g_u[b * EMBED + t];
    __syncthreads();

    for (int h = 0; h < HOPS; ++h) {
        const float* __restrict__ m = g_mw[h] + (size_t)b * STORY * EMBED;
        const float* __restrict__ c = g_cs[h] + (size_t)b * STORY * EMBED;

        // scores[s] = m[s] . u
        for (int s = w; s < STORY; s += 4) {
            const float* mr = m + s * EMBED;
            float d = mr[lane]      * u[lane]
                    + mr[lane + 32] * u[lane + 32]
                    + mr[lane + 64] * u[lane + 64]
                    + mr[lane + 96] * u[lane + 96];
#pragma unroll
            for (int o = 16; o; o >>= 1) d += __shfl_xor_sync(0xffffffffu, d, o);
            if (lane == 0) sc[s] = d;
        }
        __syncthreads();

        // softmax over STORY=50 (warp 0)
        if (t < 32) {
            float v0 = sc[t];
            float v1 = (t + 32 < STORY) ? sc[t + 32] : -3.4e38f;
            float mx = fmaxf(v0, v1);
#pragma unroll
            for (int o = 16; o; o >>= 1) mx = fmaxf(mx, __shfl_xor_sync(0xffffffffu, mx, o));
            float e0 = __expf(v0 - mx);
            float e1 = (t + 32 < STORY) ? __expf(v1 - mx) : 0.f;
            float sum = e0 + e1;
#pragma unroll
            for (int o = 16; o; o >>= 1) sum += __shfl_xor_sync(0xffffffffu, sum, o);
            float inv = 1.0f / sum;
            sc[t] = e0 * inv;
            if (t + 32 < STORY) sc[t + 32] = e1 * inv;
        }
        __syncthreads();

        // u += sum_s p[s] * c[s]
        float acc = u[t];
        for (int s = 0; s < STORY; ++s)
            acc = fmaf(sc[s], c[s * EMBED + t], acc);
        u[t] = acc;
        __syncthreads();
    }
    g_u[b * EMBED + t] = u[t];
}

// ---------------- K4a: logits = u @ A3^T, fused per-block max/sumexp ----------------
#define SMEM_LOGITS ((BATCH * EMBED + VT * 132) * 4)   // 32768 + 33792 = 66560 B

__global__ void __launch_bounds__(256) k_logits(const float* __restrict__ A3,
                                                float* __restrict__ out) {
    extern __shared__ float sh[];
    float* sU = sh;                   // [64][128]
    float* sA = sh + BATCH * EMBED;   // [64][132] padded

    const int t   = threadIdx.x;      // 256
    const int blk = blockIdx.x;
    const int v0  = blk * VT;

#pragma unroll
    for (int i = t; i < BATCH * EMBED / 4; i += 256)
        ((float4*)sU)[i] = ((const float4*)g_u)[i];

    for (int i = t; i < VT * 32; i += 256) {
        const int r = i >> 5, c = i & 31;
        const int v = v0 + r;
        float4 val = make_float4(0.f, 0.f, 0.f, 0.f);
        if (v < VOCAB) val = *(const float4*)(A3 + (size_t)v * EMBED + c * 4);
        *(float4*)(sA + r * 132 + c * 4) = val;
    }
    __syncthreads();

    const int tx = t & 15, ty = t >> 4;   // thread: 4 b = ty*4+i, 4 v = v0 + tx + j*16

    unsigned long long acc[4][4];
#pragma unroll
    for (int i = 0; i < 4; ++i)
#pragma unroll
        for (int j = 0; j < 4; ++j) acc[i][j] = 0ull;

#pragma unroll 4
    for (int k = 0; k < EMBED; k += 4) {
        ulonglong2 uu[4], aa[4];
#pragma unroll
        for (int i = 0; i < 4; ++i)
            uu[i] = *(const ulonglong2*)(sU + (ty * 4 + i) * EMBED + k);
#pragma unroll
        for (int j = 0; j < 4; ++j)
            aa[j] = *(const ulonglong2*)(sA + (tx + j * 16) * 132 + k);
#pragma unroll
        for (int i = 0; i < 4; ++i)
#pragma unroll
            for (int j = 0; j < 4; ++j) {
                ffma2(acc[i][j], uu[i].x, aa[j].x);
                ffma2(acc[i][j], uu[i].y, aa[j].y);
            }
    }

    float logit[4][4];
#pragma unroll
    for (int i = 0; i < 4; ++i)
#pragma unroll
        for (int j = 0; j < 4; ++j) {
            float2 f = *(float2*)&acc[i][j];
            logit[i][j] = f.x + f.y;
        }

    // store logits + mask invalid v
#pragma unroll
    for (int i = 0; i < 4; ++i) {
        const int b = ty * 4 + i;
#pragma unroll
        for (int j = 0; j < 4; ++j) {
            const int v = v0 + tx + j * 16;
            if (v < VOCAB) out[(size_t)b * VOCAB + v] = logit[i][j];
            else           logit[i][j] = -3.4e38f;
        }
    }

    // per-b block partials (shuffle within 16-lane tx groups)
#pragma unroll
    for (int i = 0; i < 4; ++i) {
        float m = fmaxf(fmaxf(logit[i][0], logit[i][1]), fmaxf(logit[i][2], logit[i][3]));
#pragma unroll
        for (int o = 8; o; o >>= 1) m = fmaxf(m, __shfl_xor_sync(0xffffffffu, m, o));
        float s = 0.f;
#pragma unroll
        for (int j = 0; j < 4; ++j) s += __expf(logit[i][j] - m);
#pragma unroll
        for (int o = 8; o; o >>= 1) s += __shfl_xor_sync(0xffffffffu, s, o);
        if (tx == 0) {
            const int b = ty * 4 + i;
            g_pmax[b * NBLK_V + blk] = m;
            g_psum[b * NBLK_V + blk] = s;
        }
    }
}

// ---------------- K4b: per-row logsumexp reduce ----------------
__global__ void k_lse() {
    const int b = blockIdx.x, t = threadIdx.x;   // 256
    float m = -3.4e38f, s = 0.f;
    for (int i = t; i < NBLK_V; i += 256) {
        const float bm = g_pmax[b * NBLK_V + i];
        const float bs = g_psum[b * NBLK_V + i];
        if (bm > m) { s = s * __expf(m - bm) + bs; m = bm; }
        else        { s += bs * __expf(bm - m); }
    }
    __shared__ float sm[256], ss[256];
    sm[t] = m; ss[t] = s;
    __syncthreads();
    for (int o = 128; o; o >>= 1) {
        if (t < o) {
            const float m2 = sm[t + o], s2 = ss[t + o];
            if (m2 > sm[t]) { ss[t] = ss[t] * __expf(sm[t] - m2) + s2; sm[t] = m2; }
            else            { ss[t] += s2 * __expf(m2 - sm[t]); }
        }
        __syncthreads();
    }
    if (t == 0) g_lse[b] = sm[0] + logf(ss[0]);
}

// ---------------- K4c: finalize out = logit - lse[b] ----------------
__global__ void k_final(float* __restrict__ out) {
    const int i = blockIdx.x * 256 + threadIdx.x;
    if (i >= BATCH * VOCAB / 4) return;
    const int b = (i * 4) / VOCAB;
    const float lse = g_lse[b];
    float4 v = ((float4*)out)[i];
    v.x -= lse; v.y -= lse; v.z -= lse; v.w -= lse;
    ((float4*)out)[i] = v;
}

// ---------------- launch ----------------
extern "C" void kernel_launch(void* const* d_in, const int* in_sizes, int n_in,
                              void* d_out, int out_size) {
    const int*   x  = (const int*)d_in[0];
    const int*   q  = (const int*)d_in[1];
    const float* A  = (const float*)d_in[2];
    const float* TA = (const float*)d_in[3];
    const float* TC = (const float*)d_in[4];
    float* out = (float*)d_out;

    k_u0<<<BATCH, EMBED>>>(q, A);
    k_gather<<<dim3(BATCH * STORY, HOPS + 1), 128>>>(x, A, TA, TC);
    k_hops<<<BATCH, EMBED>>>();

    cudaFuncSetAttribute(k_logits, cudaFuncAttributeMaxDynamicSharedMemorySize, SMEM_LOGITS);
    k_logits<<<NBLK_V, 256, SMEM_LOGITS>>>(A + (size_t)HOPS * VOCAB * EMBED, out);

    k_lse<<<BATCH, 256>>>();
    k_final<<<(BATCH * VOCAB / 4 + 255) / 256, 256>>>(out);
}